// round 11
// baseline (speedup 1.0000x reference)
#include <cuda_runtime.h>
#include <cuda_bf16.h>
#include <mma.h>
#include <math.h>
#include <stdint.h>

using namespace nvcuda;

#define NUM_NEURONS 2048
#define D_MODEL     1024
#define BATCH       64
#define K_TOTAL     4096
#define KSPLIT      8
#define DCHUNK      128

// Scratch (static device globals — no runtime allocation)
__device__ __align__(256) float g_xT[D_MODEL * BATCH];               // x transposed [d][b]
__device__ __align__(256) float g_S[K_TOTAL * BATCH];                // sums [k][b]
__device__ __align__(256) __nv_bfloat16 g_Ahi[BATCH * K_TOTAL];      // S^T hi  [b][k]
__device__ __align__(256) __nv_bfloat16 g_Alo[BATCH * K_TOTAL];      // S^T lo
__device__ __align__(256) __nv_bfloat16 g_Phi[D_MODEL * K_TOTAL];    // Pcat hi [j][k]
__device__ __align__(256) __nv_bfloat16 g_Plo[D_MODEL * K_TOTAL];    // Pcat lo
__device__ __align__(256) float g_part[KSPLIT * BATCH * D_MODEL];    // partials (2MB)

// ---------------------------------------------------------------------------
// Transpose x -> [d][b] so main-kernel shared stage is coalesced.
// ---------------------------------------------------------------------------
__global__ void prep_x(const float* __restrict__ x) {
    int i = blockIdx.x * 256 + threadIdx.x;   // 65536 total
    g_xT[(i & 1023) * BATCH + (i >> 10)] = x[i];
}

// ---------------------------------------------------------------------------
// Split Pcat = [proj_real | proj_imag] rows [j][k] into bf16 hi/lo.
// Runs on a side stream, hidden under the MUFU-bound main kernel.
// ---------------------------------------------------------------------------
__global__ __launch_bounds__(256) void prep_P(const float* __restrict__ Pr,
                                              const float* __restrict__ Pi) {
    #pragma unroll
    for (int it = 0; it < 4; it++) {
        int idx = blockIdx.x * 256 + threadIdx.x + it * (4096 * 256);
        int j = idx >> 12, k = idx & 4095;
        float v = (k < NUM_NEURONS) ? Pr[j * NUM_NEURONS + k]
                                    : Pi[j * NUM_NEURONS + k - NUM_NEURONS];
        __nv_bfloat16 h = __float2bfloat16(v);
        g_Phi[idx] = h;
        g_Plo[idx] = __float2bfloat16(v - __bfloat162float(h));
    }
}

// ---------------------------------------------------------------------------
// FMA-pipe sincos (R3-proven).
// ---------------------------------------------------------------------------
__device__ __forceinline__ void sincos_poly(float th, float& s_out, float& c_out) {
    const float TWO_OVER_PI = 0.636619772f;
    const float MAGIC = 12582912.0f;
    float w   = th * TWO_OVER_PI;
    float big = w + MAGIC;
    int   qi  = __float_as_int(big);
    float r   = big - MAGIC;
    float u   = w - r;
    float u2  = u * u;
    float sp  = fmaf(u2, fmaf(u2, fmaf(u2, -4.6817541e-3f, 7.9692626e-2f),
                              -6.4596410e-1f), 1.57079633f) * u;
    float cp  = fmaf(u2, fmaf(u2, fmaf(u2, -2.0864648e-2f, 2.5369510e-1f),
                              -1.2337006f), 1.0f);
    float ss = (qi & 1) ? cp : sp;
    float cc = (qi & 1) ? sp : cp;
    if (qi & 2)       ss = -ss;
    if ((qi + 1) & 2) cc = -cc;
    s_out = ss; c_out = cc;
}

// ---------------------------------------------------------------------------
// Main (R3-proven, untouched): 2 neurons x 64 batches per CTA, 3/4 MUFU +
// 1/4 FMA-pipe poly.
// ---------------------------------------------------------------------------
__global__ __launch_bounds__(128) void resonant_main(const float* __restrict__ t,
                                                     const float* __restrict__ W,
                                                     const float* __restrict__ Bp) {
    __shared__ float  x_sh[DCHUNK][BATCH];
    __shared__ float2 rB_sh[2][DCHUNK];

    int tid = threadIdx.x;
    int b   = tid & 63;
    int nl  = tid >> 6;
    int n0  = blockIdx.x * 2;

    float tb = t[b];
    float cs = 0.0f, sn = 0.0f;

    for (int d0 = 0; d0 < D_MODEL; d0 += DCHUNK) {
        float4*       xs4 = reinterpret_cast<float4*>(&x_sh[0][0]);
        const float4* xg4 = reinterpret_cast<const float4*>(g_xT + d0 * BATCH);
        #pragma unroll
        for (int i = 0; i < (DCHUNK * BATCH / 4) / 128; i++)
            xs4[tid + i * 128] = xg4[tid + i * 128];
        {
            float w0 = W [(n0 + 0) * D_MODEL + d0 + tid];
            float p0 = Bp[(n0 + 0) * D_MODEL + d0 + tid];
            rB_sh[0][tid] = make_float2(__fdividef(1.0f, 1.0f + fabsf(w0)), p0);
            float w1 = W [(n0 + 1) * D_MODEL + d0 + tid];
            float p1 = Bp[(n0 + 1) * D_MODEL + d0 + tid];
            rB_sh[1][tid] = make_float2(__fdividef(1.0f, 1.0f + fabsf(w1)), p1);
        }
        __syncthreads();

        #pragma unroll
        for (int dd = 0; dd < DCHUNK; dd += 4) {
            #pragma unroll
            for (int j = 0; j < 3; j++) {
                float2 rb = rB_sh[nl][dd + j];
                float th  = fmaf(x_sh[dd + j][b], rb.x, rb.y) + tb;
                float s, c;
                __sincosf(th, &s, &c);
                cs += c; sn += s;
            }
            {
                float2 rb = rB_sh[nl][dd + 3];
                float th  = fmaf(x_sh[dd + 3][b], rb.x, rb.y) + tb;
                float s, c;
                sincos_poly(th, s, c);
                cs += c; sn += s;
            }
        }
        __syncthreads();
    }

    int n = n0 + nl;
    g_S[n * BATCH + b]                 = cs;   // cos row: k = n
    g_S[(n + NUM_NEURONS) * BATCH + b] = sn;   // sin row: k = n + 2048
}

// ---------------------------------------------------------------------------
// S convert: transpose g_S [k][b] -> A [b][k] and split into bf16 hi/lo.
// ---------------------------------------------------------------------------
__global__ void s_convert() {
    __shared__ float tile[32][33];
    int kx = blockIdx.x * 32;
    int bx = blockIdx.y * 32;
    int tx = threadIdx.x, ty = threadIdx.y;   // (32, 8)

    #pragma unroll
    for (int i = 0; i < 4; i++)
        tile[ty + 8 * i][tx] = g_S[(kx + ty + 8 * i) * BATCH + bx + tx];
    __syncthreads();
    #pragma unroll
    for (int i = 0; i < 4; i++) {
        int b = bx + ty + 8 * i, k = kx + tx;
        float v = tile[tx][ty + 8 * i];
        __nv_bfloat16 h = __float2bfloat16(v);
        g_Ahi[b * K_TOTAL + k] = h;
        g_Alo[b * K_TOTAL + k] = __float2bfloat16(v - __bfloat162float(h));
    }
}

// ---------------------------------------------------------------------------
// Tensor-core GEMM via wmma (HMMA, legal on compute_103):
// D[b][j] = sum_k A[b][k] * Pcat[j][k], bf16 hi/lo split (3 products),
// fp32 accumulators. CTA = 64b x 64j, 8 warps, warp = 16b x 32j (2 C frags).
// Grid (16, 8): j-tiles x K-split. Operands read directly from L2-resident
// globals. Partials disjoint per ks -> deterministic.
// ---------------------------------------------------------------------------
__global__ __launch_bounds__(256) void gemm_wmma() {
    int warp = threadIdx.x >> 5;          // 0..7
    int bt   = warp >> 1;                 // 0..3
    int jt   = warp & 1;                  // 0..1
    int b0   = bt * 16;
    int j0   = blockIdx.x * 64 + jt * 32;
    int k0   = blockIdx.y * (K_TOTAL / KSPLIT);   // 512 per CTA

    wmma::fragment<wmma::matrix_a, 16, 16, 16, __nv_bfloat16, wmma::row_major> aH, aL;
    wmma::fragment<wmma::matrix_b, 16, 16, 16, __nv_bfloat16, wmma::col_major> bH0, bH1, bL0, bL1;
    wmma::fragment<wmma::accumulator, 16, 16, 16, float> c0, c1;
    wmma::fill_fragment(c0, 0.0f);
    wmma::fill_fragment(c1, 0.0f);

    const __nv_bfloat16* Ah  = g_Ahi + b0 * K_TOTAL + k0;
    const __nv_bfloat16* Al  = g_Alo + b0 * K_TOTAL + k0;
    const __nv_bfloat16* Bh0 = g_Phi + (j0 +  0) * K_TOTAL + k0;
    const __nv_bfloat16* Bh1 = g_Phi + (j0 + 16) * K_TOTAL + k0;
    const __nv_bfloat16* Bl0 = g_Plo + (j0 +  0) * K_TOTAL + k0;
    const __nv_bfloat16* Bl1 = g_Plo + (j0 + 16) * K_TOTAL + k0;

    for (int kk = 0; kk < K_TOTAL / KSPLIT; kk += 16) {
        wmma::load_matrix_sync(aH,  Ah  + kk, K_TOTAL);
        wmma::load_matrix_sync(aL,  Al  + kk, K_TOTAL);
        wmma::load_matrix_sync(bH0, Bh0 + kk, K_TOTAL);
        wmma::load_matrix_sync(bH1, Bh1 + kk, K_TOTAL);
        wmma::load_matrix_sync(bL0, Bl0 + kk, K_TOTAL);
        wmma::load_matrix_sync(bL1, Bl1 + kk, K_TOTAL);

        wmma::mma_sync(c0, aH, bH0, c0);   // hi*hi
        wmma::mma_sync(c1, aH, bH1, c1);
        wmma::mma_sync(c0, aL, bH0, c0);   // lo*hi
        wmma::mma_sync(c1, aL, bH1, c1);
        wmma::mma_sync(c0, aH, bL0, c0);   // hi*lo
        wmma::mma_sync(c1, aH, bL1, c1);
    }

    float* dst = g_part + blockIdx.y * (BATCH * D_MODEL) + b0 * D_MODEL + j0;
    wmma::store_matrix_sync(dst,      c0, D_MODEL, wmma::mem_row_major);
    wmma::store_matrix_sync(dst + 16, c1, D_MODEL, wmma::mem_row_major);
}

// ---------------------------------------------------------------------------
// Epilogue: reduce 8 partials + SiLU (proven 256x256 scalar config).
// ---------------------------------------------------------------------------
__global__ __launch_bounds__(256) void epilogue(float* __restrict__ out) {
    int i = blockIdx.x * 256 + threadIdx.x;
    float s = 0.0f;
    #pragma unroll
    for (int ks = 0; ks < KSPLIT; ks++)
        s += g_part[ks * (BATCH * D_MODEL) + i];
    out[i] = s / (1.0f + expf(-s));
}

// ---------------------------------------------------------------------------
// Inputs: x, t, W, B_p, proj_real_w, proj_imag_w, sin_table, cos_table.
// Capture-safe fork/join: the side stream is FIRST touched by a wait on an
// event recorded in the origin stream (R10's direct launch broke capture).
// ---------------------------------------------------------------------------
extern "C" void kernel_launch(void* const* d_in, const int* in_sizes, int n_in,
                              void* d_out, int out_size) {
    const float* x  = (const float*)d_in[0];
    const float* t  = (const float*)d_in[1];
    const float* W  = (const float*)d_in[2];
    const float* Bp = (const float*)d_in[3];
    const float* Pr = (const float*)d_in[4];
    const float* Pi = (const float*)d_in[5];
    float* out = (float*)d_out;

    static cudaStream_t s1 = nullptr;
    static cudaEvent_t  evFork, evP;
    if (!s1) {
        cudaStreamCreateWithFlags(&s1, cudaStreamNonBlocking);
        cudaEventCreateWithFlags(&evFork, cudaEventDisableTiming);
        cudaEventCreateWithFlags(&evP,    cudaEventDisableTiming);
    }

    // fork: bring s1 into the capture graph before launching on it
    cudaEventRecord(evFork, 0);
    cudaStreamWaitEvent(s1, evFork, 0);
    prep_P<<<4096, 256, 0, s1>>>(Pr, Pi);
    cudaEventRecord(evP, s1);

    prep_x<<<(BATCH * D_MODEL + 255) / 256, 256>>>(x);
    resonant_main<<<NUM_NEURONS / 2, 128>>>(t, W, Bp);
    s_convert<<<dim3(K_TOTAL / 32, BATCH / 32), dim3(32, 8)>>>();

    // join
    cudaStreamWaitEvent(0, evP, 0);
    gemm_wmma<<<dim3(D_MODEL / 64, KSPLIT), 256>>>();
    epilogue<<<(BATCH * D_MODEL + 255) / 256, 256>>>(out);
}

// round 12
// speedup vs baseline: 1.2553x; 1.2553x over previous
#include <cuda_runtime.h>
#include <cuda_bf16.h>
#include <mma.h>
#include <math.h>
#include <stdint.h>

using namespace nvcuda;

#define NUM_NEURONS 2048
#define D_MODEL     1024
#define BATCH       64
#define K_TOTAL     4096
#define KSPLIT      16
#define DCHUNK      128

// GEMM tiling
#define KK        32                      // k per stage
#define NSTAGE    ((K_TOTAL / KSPLIT) / KK)   // 8
#define LDM       40                      // padded row stride (bf16 elems), 80B
#define OFF_AL    (64 * LDM)              // 2560
#define OFF_BH    (2 * 64 * LDM)          // 5120
#define OFF_BL    (OFF_BH + 128 * LDM)    // 10240
#define STAGE_EL  (OFF_BL + 128 * LDM)    // 15360 bf16 per stage
#define SMEM_B    (2 * STAGE_EL * 2)      // 61440 bytes

// Scratch (static device globals — no runtime allocation)
__device__ __align__(256) float g_xT[D_MODEL * BATCH];
__device__ __align__(256) float g_S[K_TOTAL * BATCH];
__device__ __align__(256) __nv_bfloat16 g_Ahi[BATCH * K_TOTAL];
__device__ __align__(256) __nv_bfloat16 g_Alo[BATCH * K_TOTAL];
__device__ __align__(256) __nv_bfloat16 g_Phi[D_MODEL * K_TOTAL];
__device__ __align__(256) __nv_bfloat16 g_Plo[D_MODEL * K_TOTAL];
__device__ __align__(256) float g_part[KSPLIT * BATCH * D_MODEL];   // 4MB

// ---------------------------------------------------------------------------
__global__ void prep_x(const float* __restrict__ x) {
    int i = blockIdx.x * 256 + threadIdx.x;
    g_xT[(i & 1023) * BATCH + (i >> 10)] = x[i];
}

// Split Pcat rows [j][k] into bf16 hi/lo (side stream, hidden under main).
__global__ __launch_bounds__(256) void prep_P(const float* __restrict__ Pr,
                                              const float* __restrict__ Pi) {
    #pragma unroll
    for (int it = 0; it < 4; it++) {
        int idx = blockIdx.x * 256 + threadIdx.x + it * (4096 * 256);
        int j = idx >> 12, k = idx & 4095;
        float v = (k < NUM_NEURONS) ? Pr[j * NUM_NEURONS + k]
                                    : Pi[j * NUM_NEURONS + k - NUM_NEURONS];
        __nv_bfloat16 h = __float2bfloat16(v);
        g_Phi[idx] = h;
        g_Plo[idx] = __float2bfloat16(v - __bfloat162float(h));
    }
}

// ---------------------------------------------------------------------------
// FMA-pipe sincos (R3-proven).
// ---------------------------------------------------------------------------
__device__ __forceinline__ void sincos_poly(float th, float& s_out, float& c_out) {
    const float TWO_OVER_PI = 0.636619772f;
    const float MAGIC = 12582912.0f;
    float w   = th * TWO_OVER_PI;
    float big = w + MAGIC;
    int   qi  = __float_as_int(big);
    float r   = big - MAGIC;
    float u   = w - r;
    float u2  = u * u;
    float sp  = fmaf(u2, fmaf(u2, fmaf(u2, -4.6817541e-3f, 7.9692626e-2f),
                              -6.4596410e-1f), 1.57079633f) * u;
    float cp  = fmaf(u2, fmaf(u2, fmaf(u2, -2.0864648e-2f, 2.5369510e-1f),
                              -1.2337006f), 1.0f);
    float ss = (qi & 1) ? cp : sp;
    float cc = (qi & 1) ? sp : cp;
    if (qi & 2)       ss = -ss;
    if ((qi + 1) & 2) cc = -cc;
    s_out = ss; c_out = cc;
}

// ---------------------------------------------------------------------------
// Main (R3-proven, untouched).
// ---------------------------------------------------------------------------
__global__ __launch_bounds__(128) void resonant_main(const float* __restrict__ t,
                                                     const float* __restrict__ W,
                                                     const float* __restrict__ Bp) {
    __shared__ float  x_sh[DCHUNK][BATCH];
    __shared__ float2 rB_sh[2][DCHUNK];

    int tid = threadIdx.x;
    int b   = tid & 63;
    int nl  = tid >> 6;
    int n0  = blockIdx.x * 2;

    float tb = t[b];
    float cs = 0.0f, sn = 0.0f;

    for (int d0 = 0; d0 < D_MODEL; d0 += DCHUNK) {
        float4*       xs4 = reinterpret_cast<float4*>(&x_sh[0][0]);
        const float4* xg4 = reinterpret_cast<const float4*>(g_xT + d0 * BATCH);
        #pragma unroll
        for (int i = 0; i < (DCHUNK * BATCH / 4) / 128; i++)
            xs4[tid + i * 128] = xg4[tid + i * 128];
        {
            float w0 = W [(n0 + 0) * D_MODEL + d0 + tid];
            float p0 = Bp[(n0 + 0) * D_MODEL + d0 + tid];
            rB_sh[0][tid] = make_float2(__fdividef(1.0f, 1.0f + fabsf(w0)), p0);
            float w1 = W [(n0 + 1) * D_MODEL + d0 + tid];
            float p1 = Bp[(n0 + 1) * D_MODEL + d0 + tid];
            rB_sh[1][tid] = make_float2(__fdividef(1.0f, 1.0f + fabsf(w1)), p1);
        }
        __syncthreads();

        #pragma unroll
        for (int dd = 0; dd < DCHUNK; dd += 4) {
            #pragma unroll
            for (int j = 0; j < 3; j++) {
                float2 rb = rB_sh[nl][dd + j];
                float th  = fmaf(x_sh[dd + j][b], rb.x, rb.y) + tb;
                float s, c;
                __sincosf(th, &s, &c);
                cs += c; sn += s;
            }
            {
                float2 rb = rB_sh[nl][dd + 3];
                float th  = fmaf(x_sh[dd + 3][b], rb.x, rb.y) + tb;
                float s, c;
                sincos_poly(th, s, c);
                cs += c; sn += s;
            }
        }
        __syncthreads();
    }

    int n = n0 + nl;
    g_S[n * BATCH + b]                 = cs;
    g_S[(n + NUM_NEURONS) * BATCH + b] = sn;
}

// ---------------------------------------------------------------------------
// S convert: transpose g_S [k][b] -> A [b][k], split bf16 hi/lo.
// ---------------------------------------------------------------------------
__global__ void s_convert() {
    __shared__ float tile[32][33];
    int kx = blockIdx.x * 32;
    int bx = blockIdx.y * 32;
    int tx = threadIdx.x, ty = threadIdx.y;   // (32, 8)

    #pragma unroll
    for (int i = 0; i < 4; i++)
        tile[ty + 8 * i][tx] = g_S[(kx + ty + 8 * i) * BATCH + bx + tx];
    __syncthreads();
    #pragma unroll
    for (int i = 0; i < 4; i++) {
        int b = bx + ty + 8 * i, k = kx + tx;
        float v = tile[tx][ty + 8 * i];
        __nv_bfloat16 h = __float2bfloat16(v);
        g_Ahi[b * K_TOTAL + k] = h;
        g_Alo[b * K_TOTAL + k] = __float2bfloat16(v - __bfloat162float(h));
    }
}

// ---------------------------------------------------------------------------
// Tensor-core GEMM, smem-staged (LDSM path) + double buffer + reg prefetch.
// CTA = 64b x 128j, 8 warps of 32x32 (2x2 C frags). KSPLIT=16, K=256/CTA,
// 8 stages of KK=32. bf16 hi/lo split: hi*hi + lo*hi + hi*lo, fp32 acc.
// Grid (8, 16) = 128 CTAs; disjoint partials -> deterministic.
// ---------------------------------------------------------------------------
__global__ __launch_bounds__(256) void gemm_wmma() {
    extern __shared__ __nv_bfloat16 sm[];

    int tid  = threadIdx.x;
    int warp = tid >> 5;
    int wb   = (warp >> 2) * 32;          // warp b offset: 0 or 32
    int wj   = (warp & 3) * 32;           // warp j offset: 0..96
    int j0   = blockIdx.x * 128;
    int k0   = blockIdx.y * (K_TOTAL / KSPLIT);

    // global staging ownership
    int arow = tid >> 2, achk = (tid & 3) * 8;   // A: 64 rows x 4 chunks
    const __nv_bfloat16* gAh = g_Ahi + arow * K_TOTAL + k0 + achk;
    const __nv_bfloat16* gAl = g_Alo + arow * K_TOTAL + k0 + achk;
    // B: 128 rows x 4 chunks = 512 slots, 2 per thread
    int brow0 = tid >> 1, bchk0 = (tid & 1) * 16;          // chunks 0/2 base: use pairs
    const __nv_bfloat16* gBh = g_Phi + (j0 + brow0) * K_TOTAL + k0 + bchk0;
    const __nv_bfloat16* gBl = g_Plo + (j0 + brow0) * K_TOTAL + k0 + bchk0;

    uint32_t aDst = arow * LDM + achk;            // smem elem offsets
    uint32_t bDst = brow0 * LDM + bchk0;

    wmma::fragment<wmma::matrix_a, 16, 16, 16, __nv_bfloat16, wmma::row_major> aH[2], aL[2];
    wmma::fragment<wmma::matrix_b, 16, 16, 16, __nv_bfloat16, wmma::col_major> bH[2], bL[2];
    wmma::fragment<wmma::accumulator, 16, 16, 16, float> c[2][2];
    #pragma unroll
    for (int i = 0; i < 2; i++)
        #pragma unroll
        for (int j = 0; j < 2; j++) wmma::fill_fragment(c[i][j], 0.0f);

    // stage 0: global -> smem directly
    {
        __nv_bfloat16* st = sm;
        *reinterpret_cast<uint4*>(st + aDst)          = *reinterpret_cast<const uint4*>(gAh);
        *reinterpret_cast<uint4*>(st + OFF_AL + aDst) = *reinterpret_cast<const uint4*>(gAl);
        #pragma unroll
        for (int q = 0; q < 2; q++) {
            *reinterpret_cast<uint4*>(st + OFF_BH + bDst + q * 8) =
                *reinterpret_cast<const uint4*>(gBh + q * 8);
            *reinterpret_cast<uint4*>(st + OFF_BL + bDst + q * 8) =
                *reinterpret_cast<const uint4*>(gBl + q * 8);
        }
    }
    __syncthreads();

    uint4 rAh, rAl, rBh[2], rBl[2];

    for (int s = 0; s < NSTAGE; s++) {
        if (s + 1 < NSTAGE) {             // prefetch next stage into regs
            int off = (s + 1) * KK;
            rAh = *reinterpret_cast<const uint4*>(gAh + off);
            rAl = *reinterpret_cast<const uint4*>(gAl + off);
            #pragma unroll
            for (int q = 0; q < 2; q++) {
                rBh[q] = *reinterpret_cast<const uint4*>(gBh + off + q * 8);
                rBl[q] = *reinterpret_cast<const uint4*>(gBl + off + q * 8);
            }
        }

        // compute current stage (2 k-steps of 16)
        const __nv_bfloat16* st = sm + (s & 1) * STAGE_EL;
        #pragma unroll
        for (int ks = 0; ks < 2; ks++) {
            int kc = ks * 16;
            wmma::load_matrix_sync(aH[0], st + (wb +  0) * LDM + kc, LDM);
            wmma::load_matrix_sync(aH[1], st + (wb + 16) * LDM + kc, LDM);
            wmma::load_matrix_sync(aL[0], st + OFF_AL + (wb +  0) * LDM + kc, LDM);
            wmma::load_matrix_sync(aL[1], st + OFF_AL + (wb + 16) * LDM + kc, LDM);
            wmma::load_matrix_sync(bH[0], st + OFF_BH + (wj +  0) * LDM + kc, LDM);
            wmma::load_matrix_sync(bH[1], st + OFF_BH + (wj + 16) * LDM + kc, LDM);
            wmma::load_matrix_sync(bL[0], st + OFF_BL + (wj +  0) * LDM + kc, LDM);
            wmma::load_matrix_sync(bL[1], st + OFF_BL + (wj + 16) * LDM + kc, LDM);
            #pragma unroll
            for (int i = 0; i < 2; i++)
                #pragma unroll
                for (int j = 0; j < 2; j++) {
                    wmma::mma_sync(c[i][j], aH[i], bH[j], c[i][j]);
                    wmma::mma_sync(c[i][j], aL[i], bH[j], c[i][j]);
                    wmma::mma_sync(c[i][j], aH[i], bL[j], c[i][j]);
                }
        }

        if (s + 1 < NSTAGE) {             // commit prefetched regs to other buffer
            __syncthreads();              // everyone done reading buf (s+1)&1 from stage s-1
            __nv_bfloat16* dt = sm + ((s + 1) & 1) * STAGE_EL;
            *reinterpret_cast<uint4*>(dt + aDst)          = rAh;
            *reinterpret_cast<uint4*>(dt + OFF_AL + aDst) = rAl;
            #pragma unroll
            for (int q = 0; q < 2; q++) {
                *reinterpret_cast<uint4*>(dt + OFF_BH + bDst + q * 8) = rBh[q];
                *reinterpret_cast<uint4*>(dt + OFF_BL + bDst + q * 8) = rBl[q];
            }
            __syncthreads();
        }
    }

    float* dst = g_part + blockIdx.y * (BATCH * D_MODEL);
    #pragma unroll
    for (int i = 0; i < 2; i++)
        #pragma unroll
        for (int j = 0; j < 2; j++)
            wmma::store_matrix_sync(dst + (wb + i * 16) * D_MODEL + j0 + wj + j * 16,
                                    c[i][j], D_MODEL, wmma::mem_row_major);
}

// ---------------------------------------------------------------------------
// Epilogue: reduce KSPLIT partials + SiLU (proven 256x256 scalar config).
// ---------------------------------------------------------------------------
__global__ __launch_bounds__(256) void epilogue(float* __restrict__ out) {
    int i = blockIdx.x * 256 + threadIdx.x;
    float s = 0.0f;
    #pragma unroll
    for (int ks = 0; ks < KSPLIT; ks++)
        s += g_part[ks * (BATCH * D_MODEL) + i];
    out[i] = s / (1.0f + expf(-s));
}

// ---------------------------------------------------------------------------
// Capture-safe fork/join (R11-proven). Inputs: x, t, W, B_p, Pr, Pi, tables.
// ---------------------------------------------------------------------------
extern "C" void kernel_launch(void* const* d_in, const int* in_sizes, int n_in,
                              void* d_out, int out_size) {
    const float* x  = (const float*)d_in[0];
    const float* t  = (const float*)d_in[1];
    const float* W  = (const float*)d_in[2];
    const float* Bp = (const float*)d_in[3];
    const float* Pr = (const float*)d_in[4];
    const float* Pi = (const float*)d_in[5];
    float* out = (float*)d_out;

    static cudaStream_t s1 = nullptr;
    static cudaEvent_t  evFork, evP;
    if (!s1) {
        cudaStreamCreateWithFlags(&s1, cudaStreamNonBlocking);
        cudaEventCreateWithFlags(&evFork, cudaEventDisableTiming);
        cudaEventCreateWithFlags(&evP,    cudaEventDisableTiming);
        cudaFuncSetAttribute(gemm_wmma, cudaFuncAttributeMaxDynamicSharedMemorySize, SMEM_B);
    }

    cudaEventRecord(evFork, 0);
    cudaStreamWaitEvent(s1, evFork, 0);
    prep_P<<<4096, 256, 0, s1>>>(Pr, Pi);
    cudaEventRecord(evP, s1);

    prep_x<<<(BATCH * D_MODEL + 255) / 256, 256>>>(x);
    resonant_main<<<NUM_NEURONS / 2, 128>>>(t, W, Bp);
    s_convert<<<dim3(K_TOTAL / 32, BATCH / 32), dim3(32, 8)>>>();

    cudaStreamWaitEvent(0, evP, 0);
    gemm_wmma<<<dim3(D_MODEL / 128, KSPLIT), 256, SMEM_B>>>();
    epilogue<<<(BATCH * D_MODEL + 255) / 256, 256>>>(out);
}